// round 6
// baseline (speedup 1.0000x reference)
#include <cuda_runtime.h>
#include <math.h>

// Device-global accumulator. Starts at 0 (static init); finalize_kernel
// resets it to 0 after reading, so every graph replay sees 0.
__device__ double g_sum = 0.0;

// ---------------------------------------------------------------------------
// Main kernel, warp-specialized: global warp W processes transform k = W % 6
// applied to the 32 points starting at (W/6)*32. Each thread does exactly one
// transform + one 3-float gather -> short dependency chain, max occupancy.
// ---------------------------------------------------------------------------
__global__ void __launch_bounds__(256)
main_kernel(const float* __restrict__ pts,
            const float4* __restrict__ planes4,   // 3 rows of (nx,ny,nz,d)
            const float4* __restrict__ axes4,     // 3 rows of (w,x,y,z)
            const float* __restrict__ grid,
            const float* __restrict__ gmin,
            const float* __restrict__ gmax,
            int N, int R)
{
    unsigned W    = blockIdx.x * 8u + (threadIdx.x >> 5);  // global warp id
    unsigned k    = W % 6u;                                // transform id (warp-uniform)
    int      lane = threadIdx.x & 31;
    int      i    = (int)((W / 6u) << 5) + lane;           // point index

    float gx = __ldg(gmin), gy = __ldg(gmin + 1), gz = __ldg(gmin + 2);
    float sx = (float)(R - 1) / (__ldg(gmax)     - gx);
    float sy = (float)(R - 1) / (__ldg(gmax + 1) - gy);
    float sz = (float)(R - 1) / (__ldg(gmax + 2) - gz);
    unsigned strideY = (unsigned)(R * 3);
    unsigned strideX = strideY * (unsigned)R;
    int Rm1 = R - 1;

    float local = 0.f;

    if (i < N) {
        float px = __ldg(pts + 3 * i);
        float py = __ldg(pts + 3 * i + 1);
        float pz = __ldg(pts + 3 * i + 2);

        float tx, ty, tz;
        if (k < 3u) {
            // Plane reflection with row k
            float4 pl = __ldg(planes4 + k);
            float proj = px * pl.x + py * pl.y + pz * pl.z + pl.w;
            tx = px - 2.f * proj * pl.x;
            ty = py - 2.f * proj * pl.y;
            tz = pz - 2.f * proj * pl.z;
        } else {
            // Quaternion rotation with row k-3 (q NOT normalized — matches ref)
            float4 q = __ldg(axes4 + (k - 3u));
            float w = q.x, x = q.y, y = q.z, z = q.w;
            float tw = -x * px - y * py - z * pz;
            float qx =  w * px + y * pz - z * py;
            float qy =  w * py - x * pz + z * px;
            float qz =  w * pz + x * py - y * px;
            tx = -tw * x + qx * w - qy * z + qz * y;
            ty = -tw * y + qx * z + qy * w - qz * x;
            tz = -tw * z - qx * y + qy * x + qz * w;
        }

        // Nearest grid cell (round-half-even = jnp.round), clamp, gather.
        int ix = __float2int_rn((tx - gx) * sx);
        int iy = __float2int_rn((ty - gy) * sy);
        int iz = __float2int_rn((tz - gz) * sz);
        ix = min(max(ix, 0), Rm1);
        iy = min(max(iy, 0), Rm1);
        iz = min(max(iz, 0), Rm1);
        unsigned off = (unsigned)ix * strideX + (unsigned)iy * strideY + (unsigned)iz * 3u;
        float cx = __ldg(grid + off);
        float cy = __ldg(grid + off + 1u);
        float cz = __ldg(grid + off + 2u);
        float dx = tx - cx, dy = ty - cy, dz = tz - cz;
        local = sqrtf(fmaf(dx, dx, fmaf(dy, dy, dz * dz)));
    }

    // Warp reduce
    #pragma unroll
    for (int off = 16; off > 0; off >>= 1)
        local += __shfl_down_sync(0xFFFFFFFFu, local, off);

    // Block reduce (8 warps)
    __shared__ float warp_sums[8];
    int wid = threadIdx.x >> 5;
    if (lane == 0) warp_sums[wid] = local;
    __syncthreads();
    if (wid == 0) {
        float s = (lane < 8) ? warp_sums[lane] : 0.f;
        #pragma unroll
        for (int off = 4; off > 0; off >>= 1)
            s += __shfl_down_sync(0xFFFFFFFFu, s, off);
        if (lane == 0)
            atomicAdd(&g_sum, (double)s);
    }
}

// ---------------------------------------------------------------------------
// Finalize (1 thread): regularizer + outputs + reset accumulator for replay.
// ---------------------------------------------------------------------------
__global__ void finalize_kernel(const float* __restrict__ planes,
                                const float* __restrict__ axes,
                                float* __restrict__ out,
                                int out_size, int N)
{
    double total = g_sum;
    g_sum = 0.0;   // reset for next graph replay

    float n[3][3], v[3][3];
    #pragma unroll
    for (int r = 0; r < 3; r++) {
        #pragma unroll
        for (int c = 0; c < 3; c++)
            n[r][c] = planes[r * 4 + c];
        float x = axes[r * 4 + 1];
        float y = axes[r * 4 + 2];
        float z = axes[r * 4 + 3];
        float nrm = sqrtf(x * x + y * y + z * z);
        float inv = 1.f / fmaxf(nrm, 1e-12f);
        v[r][0] = x * inv; v[r][1] = y * inv; v[r][2] = z * inv;
    }
    float sumA2 = 0.f, sumB2 = 0.f;
    #pragma unroll
    for (int r = 0; r < 3; r++)
        #pragma unroll
        for (int c = 0; c < 3; c++) {
            float da = n[r][0] * n[c][0] + n[r][1] * n[c][1] + n[r][2] * n[c][2]
                     - (r == c ? 1.f : 0.f);
            float db = v[r][0] * v[c][0] + v[r][1] * v[c][1] + v[r][2] * v[c][2]
                     - (r == c ? 1.f : 0.f);
            sumA2 += da * da;
            sumB2 += db * db;
        }

    float loss_r = sumA2 + sumB2;
    float sd  = (float)(total / (double)N);
    float fin = sd + 25.0f * loss_r;
    out[0] = fin;
    if (out_size > 1) out[1] = sd;
    if (out_size > 2) out[2] = loss_r;
}

// ---------------------------------------------------------------------------
extern "C" void kernel_launch(void* const* d_in, const int* in_sizes, int n_in,
                              void* d_out, int out_size)
{
    const float* planes = (const float*)d_in[0];   // (1,3,4)
    const float* axes   = (const float*)d_in[1];   // (1,3,4)
    const float* pts    = (const float*)d_in[2];   // (N,3)
    const float* grid   = (const float*)d_in[3];   // (R,R,R,3)
    const float* gmin   = (const float*)d_in[4];   // (3,)
    const float* gmax   = (const float*)d_in[5];   // (3,)

    int N = in_sizes[2] / 3;
    long gelems = (long)in_sizes[3] / 3;
    int R = (int)llrintf(cbrtf((float)gelems));

    // 6 transforms per 32-point tile, one warp each.
    unsigned pointTiles = (unsigned)((N + 31) / 32);
    unsigned totalWarps = pointTiles * 6u;
    unsigned blocks     = (totalWarps + 7u) / 8u;   // 8 warps per 256-thread block

    main_kernel<<<blocks, 256>>>(pts, (const float4*)planes, (const float4*)axes,
                                 grid, gmin, gmax, N, R);
    finalize_kernel<<<1, 1>>>(planes, axes, (float*)d_out, out_size, N);
}

// round 7
// speedup vs baseline: 1.7382x; 1.7382x over previous
#include <cuda_runtime.h>
#include <math.h>

// Device-global accumulators. g_sum starts 0 (static init); finalize resets it
// after reading so every graph replay sees 0. g_loss_r overwritten every launch.
__device__ double g_sum = 0.0;
__device__ float  g_loss_r = 0.0f;

// ---------------------------------------------------------------------------
// Grid distance: nearest cell (round-half-even = jnp.round), integer clamp,
// gather 3 floats, return |tp - cp|.
// ---------------------------------------------------------------------------
__device__ __forceinline__ float grid_dist(float tx, float ty, float tz,
                                           const float* __restrict__ grid,
                                           float gx, float gy, float gz,
                                           float sx, float sy, float sz,
                                           int Rm1, unsigned strideX, unsigned strideY)
{
    int ix = __float2int_rn((tx - gx) * sx);
    int iy = __float2int_rn((ty - gy) * sy);
    int iz = __float2int_rn((tz - gz) * sz);
    ix = min(max(ix, 0), Rm1);
    iy = min(max(iy, 0), Rm1);
    iz = min(max(iz, 0), Rm1);
    unsigned off = (unsigned)ix * strideX + (unsigned)iy * strideY + (unsigned)iz * 3u;
    float cx = __ldg(grid + off);
    float cy = __ldg(grid + off + 1u);
    float cz = __ldg(grid + off + 2u);
    float dx = tx - cx, dy = ty - cy, dz = tz - cz;
    return sqrtf(fmaf(dx, dx, fmaf(dy, dy, dz * dz)));
}

// ---------------------------------------------------------------------------
// All 6 transforms + gathers for one point.
// ---------------------------------------------------------------------------
__device__ __forceinline__ float point_loss(float px, float py, float pz,
                                            const float4* __restrict__ planes4,
                                            const float4* __restrict__ axes4,
                                            const float* __restrict__ grid,
                                            float gx, float gy, float gz,
                                            float sx, float sy, float sz,
                                            int Rm1, unsigned strideX, unsigned strideY)
{
    float acc = 0.f;

    #pragma unroll
    for (int k = 0; k < 3; k++) {
        float4 pl = __ldg(planes4 + k);
        float proj = px * pl.x + py * pl.y + pz * pl.z + pl.w;
        float rx = px - 2.f * proj * pl.x;
        float ry = py - 2.f * proj * pl.y;
        float rz = pz - 2.f * proj * pl.z;
        acc += grid_dist(rx, ry, rz, grid, gx, gy, gz, sx, sy, sz, Rm1, strideX, strideY);
    }

    #pragma unroll
    for (int k = 0; k < 3; k++) {
        float4 q = __ldg(axes4 + k);
        float w = q.x, x = q.y, y = q.z, z = q.w;
        float tw = -x * px - y * py - z * pz;
        float qx =  w * px + y * pz - z * py;
        float qy =  w * py - x * pz + z * px;
        float qz =  w * pz + x * py - y * px;
        float rx = -tw * x + qx * w - qy * z + qz * y;
        float ry = -tw * y + qx * z + qy * w - qz * x;
        float rz = -tw * z - qx * y + qy * x + qz * w;
        acc += grid_dist(rx, ry, rz, grid, gx, gy, gz, sx, sy, sz, Rm1, strideX, strideY);
    }

    return acc;
}

// ---------------------------------------------------------------------------
// Main kernel: 2 points/thread (float2-vectorized point loads), 12 gathers,
// block reduce, one double atomic per block. Regs capped at ~40.
// ---------------------------------------------------------------------------
__global__ void __launch_bounds__(256, 6)
main_kernel(const float2* __restrict__ pts2,
            const float4* __restrict__ planes4,
            const float4* __restrict__ axes4,
            const float* __restrict__ grid,
            const float* __restrict__ gmin,
            const float* __restrict__ gmax,
            int N, int R)
{
    int t = blockIdx.x * blockDim.x + threadIdx.x;   // thread = 2 points

    float gx = __ldg(gmin), gy = __ldg(gmin + 1), gz = __ldg(gmin + 2);
    float sx = (float)(R - 1) / (__ldg(gmax)     - gx);
    float sy = (float)(R - 1) / (__ldg(gmax + 1) - gy);
    float sz = (float)(R - 1) / (__ldg(gmax + 2) - gz);
    unsigned strideY = (unsigned)(R * 3);
    unsigned strideX = strideY * (unsigned)R;
    int Rm1 = R - 1;

    float local = 0.f;

    int i0 = 2 * t;
    if (i0 < N) {
        // 6 consecutive floats at float2 index 3t (always 8B aligned).
        float2 a = __ldg(pts2 + 3 * t);
        float2 b = __ldg(pts2 + 3 * t + 1);

        local += point_loss(a.x, a.y, b.x, planes4, axes4, grid,
                            gx, gy, gz, sx, sy, sz, Rm1, strideX, strideY);

        if (i0 + 1 < N) {
            float2 c = __ldg(pts2 + 3 * t + 2);
            local += point_loss(b.y, c.x, c.y, planes4, axes4, grid,
                                gx, gy, gz, sx, sy, sz, Rm1, strideX, strideY);
        }
    }

    // Warp reduce
    #pragma unroll
    for (int off = 16; off > 0; off >>= 1)
        local += __shfl_down_sync(0xFFFFFFFFu, local, off);

    // Block reduce
    __shared__ float warp_sums[8];
    int lane = threadIdx.x & 31;
    int wid  = threadIdx.x >> 5;
    if (lane == 0) warp_sums[wid] = local;
    __syncthreads();
    if (wid == 0) {
        float s = (lane < 8) ? warp_sums[lane] : 0.f;
        #pragma unroll
        for (int off = 4; off > 0; off >>= 1)
            s += __shfl_down_sync(0xFFFFFFFFu, s, off);
        if (lane == 0)
            atomicAdd(&g_sum, (double)s);
    }

    // Regularizer (independent of the reduction): one thread computes it.
    if (blockIdx.x == 0 && threadIdx.x == 0) {
        float n[3][3], v[3][3];
        #pragma unroll
        for (int r = 0; r < 3; r++) {
            float4 pl = __ldg(planes4 + r);
            n[r][0] = pl.x; n[r][1] = pl.y; n[r][2] = pl.z;
            float4 q = __ldg(axes4 + r);
            float nrm = sqrtf(q.y * q.y + q.z * q.z + q.w * q.w);
            float inv = 1.f / fmaxf(nrm, 1e-12f);
            v[r][0] = q.y * inv; v[r][1] = q.z * inv; v[r][2] = q.w * inv;
        }
        float sumA2 = 0.f, sumB2 = 0.f;
        #pragma unroll
        for (int r = 0; r < 3; r++)
            #pragma unroll
            for (int c = 0; c < 3; c++) {
                float da = n[r][0] * n[c][0] + n[r][1] * n[c][1] + n[r][2] * n[c][2]
                         - (r == c ? 1.f : 0.f);
                float db = v[r][0] * v[c][0] + v[r][1] * v[c][1] + v[r][2] * v[c][2]
                         - (r == c ? 1.f : 0.f);
                sumA2 += da * da;
                sumB2 += db * db;
            }
        g_loss_r = sumA2 + sumB2;
    }
}

// ---------------------------------------------------------------------------
// Finalize (1 thread): read accumulators, write outputs, reset for replay.
// ---------------------------------------------------------------------------
__global__ void finalize_kernel(float* __restrict__ out, int out_size, int N)
{
    double total = g_sum;
    g_sum = 0.0;   // reset for next graph replay
    float loss_r = g_loss_r;

    float sd  = (float)(total / (double)N);
    float fin = sd + 25.0f * loss_r;
    out[0] = fin;
    if (out_size > 1) out[1] = sd;
    if (out_size > 2) out[2] = loss_r;
}

// ---------------------------------------------------------------------------
extern "C" void kernel_launch(void* const* d_in, const int* in_sizes, int n_in,
                              void* d_out, int out_size)
{
    const float* planes = (const float*)d_in[0];   // (1,3,4)
    const float* axes   = (const float*)d_in[1];   // (1,3,4)
    const float* pts    = (const float*)d_in[2];   // (N,3)
    const float* grid   = (const float*)d_in[3];   // (R,R,R,3)
    const float* gmin   = (const float*)d_in[4];   // (3,)
    const float* gmax   = (const float*)d_in[5];   // (3,)

    int N = in_sizes[2] / 3;
    long gelems = (long)in_sizes[3] / 3;
    int R = (int)llrintf(cbrtf((float)gelems));

    int threads = 256;
    int pairs   = (N + 1) / 2;
    int blocks  = (pairs + threads - 1) / threads;

    main_kernel<<<blocks, threads>>>((const float2*)pts, (const float4*)planes,
                                     (const float4*)axes, grid, gmin, gmax, N, R);
    finalize_kernel<<<1, 1>>>((float*)d_out, out_size, N);
}